// round 14
// baseline (speedup 1.0000x reference)
#include <cuda_runtime.h>
#include <cuda_bf16.h>
#include <cstdint>

// NCA 3D update step — fused conv+GEMM (bf16 HMMA), 8x16 tile, 3 CTAs/SM
// (24 warps/SM for latency hiding), TZ=4 for 92% wave occupancy.
//   x:[4,64,64,64,16] f32, w0:[128,64], b0:[128], w1:[16,128], stoch:[4,64^3,1]
// out = (x + dx*(stoch>0.5)) * (pre_life & alive(x2))
// y is K-PERMUTED in YS smem: y'[4c+s] = {x_c, gx_c, gy_c, gz_c}; 1/32 in W0.
// Swizzle s(row) = (row&7)^((row>>4)&7).

#define SB 4
#define SS 64
#define SC 16
#define NVOX (SB * SS * SS * SS)

__device__ float         g_alpha_buf[NVOX + 32];
#define G_ALPHA (g_alpha_buf + 16)
__device__ unsigned char g_pre[NVOX];

__device__ __forceinline__ uint32_t smem_u32(const void* p) {
    uint32_t a;
    asm("{ .reg .u64 t; cvta.to.shared.u64 t, %1; cvt.u32.u64 %0, t; }" : "=r"(a) : "l"(p));
    return a;
}
__device__ __forceinline__ uint32_t pack_bf16x2(float lo, float hi) {
    uint32_t r;
    asm("cvt.rn.bf16x2.f32 %0, %1, %2;" : "=r"(r) : "f"(hi), "f"(lo));
    return r;
}
__device__ __forceinline__ void mma_bf16(float* c, const uint32_t* a, const uint2 b) {
    asm volatile(
        "mma.sync.aligned.m16n8k16.row.col.f32.bf16.bf16.f32 "
        "{%0,%1,%2,%3}, {%4,%5,%6,%7}, {%8,%9}, {%0,%1,%2,%3};"
        : "+f"(c[0]), "+f"(c[1]), "+f"(c[2]), "+f"(c[3])
        : "r"(a[0]), "r"(a[1]), "r"(a[2]), "r"(a[3]), "r"(b.x), "r"(b.y));
}
#define LDMATRIX_X4(r, addr)                                                   \
    asm volatile("ldmatrix.sync.aligned.m8n8.x4.shared.b16 {%0,%1,%2,%3}, [%4];" \
        : "=r"((r)[0]), "=r"((r)[1]), "=r"((r)[2]), "=r"((r)[3]) : "r"(addr))

__device__ __forceinline__ uint64_t f2fma(uint64_t a, uint64_t b, uint64_t c) {
    uint64_t d; asm("fma.rn.f32x2 %0, %1, %2, %3;" : "=l"(d) : "l"(a), "l"(b), "l"(c)); return d;
}
__device__ __forceinline__ uint64_t f2add(uint64_t a, uint64_t b) {
    uint64_t d; asm("add.rn.f32x2 %0, %1, %2;" : "=l"(d) : "l"(a), "l"(b)); return d;
}
__device__ __forceinline__ float2 upk(uint64_t v) {
    uint32_t lo, hi; asm("mov.b64 {%0, %1}, %2;" : "=r"(lo), "=r"(hi) : "l"(v));
    return make_float2(__uint_as_float(lo), __uint_as_float(hi));
}
__device__ __forceinline__ uint64_t pk(float x, float y) {
    uint64_t v;
    asm("mov.b64 %0, {%1, %2};" : "=l"(v) : "r"(__float_as_uint(x)), "r"(__float_as_uint(y)));
    return v;
}
#define TWO2 0x4000000040000000ull
#define NEG2 0xBF800000BF800000ull

#define YSW(row) (((row) & 7) ^ (((row) >> 4) & 7))

#define TY 8
#define TX 16
#define TZ 4
#define XROW 18
#define HROWS (TY + 2)                 // 10
#define XS_PLANE (HROWS * XROW)        // 180
#define XS_CH    (3 * XS_PLANE)        // 540
#define XS_BYTES (16 * XS_CH * 4)      // 34560
#define YS_BYTES (128 * 128)           // 16384
#define F_SMEM_BYTES (XS_BYTES + YS_BYTES + 16384 + 4096)   // 71424 -> 3 CTAs/SM

__device__ __forceinline__ void load_plane(float* XS, const float* __restrict__ x,
                                           int b, int zp, int ty0, int tx0,
                                           int slot, int tid) {
    const bool zin = (zp >= 0 && zp < SS);
    for (int i = tid; i < XS_PLANE; i += 256) {
        int hy = i / XROW;
        int wx = i % XROW;
        int dst = slot * XS_PLANE + i;
        int gy2 = hy - 1 + ty0, gx2 = wx - 1 + tx0;
        if (zin && gy2 >= 0 && gy2 < SS && gx2 >= 0 && gx2 < SS) {
            const float4* p = (const float4*)(x + ((((size_t)b * SS + zp) * SS + gy2) * SS + gx2) * SC);
#pragma unroll
            for (int q = 0; q < 4; q++) {
                float4 v = p[q];
                XS[(4 * q + 0) * XS_CH + dst] = v.x;
                XS[(4 * q + 1) * XS_CH + dst] = v.y;
                XS[(4 * q + 2) * XS_CH + dst] = v.z;
                XS[(4 * q + 3) * XS_CH + dst] = v.w;
            }
        } else {
#pragma unroll
            for (int c = 0; c < 16; c++) XS[c * XS_CH + dst] = 0.f;
        }
    }
}

#define NPF 3   // 720 16B-chunks / 256 threads

__global__ __launch_bounds__(256, 3)
void nca_fused(const float* __restrict__ x, const float* __restrict__ w0g,
               const float* __restrict__ w1g, const float* __restrict__ b0,
               const float* __restrict__ stoch, float* __restrict__ out) {
    extern __shared__ float SM[];
    float*   XS  = SM;
    uint8_t* YS  = (uint8_t*)(SM + 16 * XS_CH);
    uint8_t* W0S = YS + YS_BYTES;
    uint8_t* W1S = W0S + 16384;

    const int tid = threadIdx.x;

    // ---- weights -> smem (bf16, swizzled, K-permuted, scaled) ----
    for (int t = tid; t < 128 * 32; t += 256) {
        int n = t >> 5, k2 = t & 31;
        float e[2];
#pragma unroll
        for (int q = 0; q < 2; q++) {
            int kp = 2 * k2 + q;
            int ko = (kp & 3) * 16 + (kp >> 2);
            float s = (ko >= 16) ? (1.f / 32.f) : 1.f;
            e[q] = w0g[n * 64 + ko] * s;
        }
        int c16 = k2 >> 2;
        *(uint32_t*)(W0S + n * 128 + ((c16 ^ YSW(n)) << 4) + (k2 & 3) * 4) =
            pack_bf16x2(e[0], e[1]);
    }
    for (int t = tid; t < 32 * 32; t += 256) {
        int r = t >> 5, k2 = t & 31;
        int n = r & 15, half = r >> 4;
        int k = half * 64 + 2 * k2;
        int c16 = k2 >> 2;
        *(uint32_t*)(W1S + r * 128 + ((c16 ^ YSW(r)) << 4) + (k2 & 3) * 4) =
            pack_bf16x2(w1g[n * 128 + k], w1g[n * 128 + k + 1]);
    }

    const int b   = blockIdx.z >> 4;
    const int z0  = (blockIdx.z & 15) * TZ;
    const int ty0 = blockIdx.y * TY;
    const int tx0 = blockIdx.x * TX;

    load_plane(XS, x, b, z0 - 1, ty0, tx0, ((z0 - 1) + 3) % 3, tid);
    load_plane(XS, x, b, z0,     ty0, tx0, z0 % 3,             tid);
    load_plane(XS, x, b, z0 + 1, ty0, tx0, (z0 + 1) % 3,       tid);

    // conv mapping: cpgrp(8 channel-pairs) x [ly(8), tx4(4 groups of 4 x)]
    const int cpgrp = tid >> 5;
    const int sub   = tid & 31;
    const int ly    = sub & 7;
    const int tx4   = sub >> 3;
    const int gh    = ty0 + ly;
    const int gx0   = tx0 + 4 * tx4;

    // gemm mapping: warp w handles m-tile w (rows w*16..w*16+15)
    const int w    = tid >> 5;
    const int lane = tid & 31;
    const int g    = lane >> 2;
    const int tg   = lane & 3;
    const int l7   = lane & 7;
    const int sel  = lane >> 3;

    __syncthreads();

    for (int z = z0; z < z0 + TZ; z++) {
        const int s0 = ((z - 1) + 3) % 3, s1 = z % 3, s2 = (z + 1) % 3;
        const size_t voxbase = (((size_t)b * SS + z) * SS + gh) * SS + gx0;
        const int lrow0 = ly * TX + 4 * tx4;

        // ---------------- conv phase (f32x2, jp-outer for low reg pressure) --
        {
            float st[2][4][4];
#pragma unroll
            for (int ci = 0; ci < 2; ci++) {
                const int c = cpgrp * 2 + ci;
                const float* base = XS + c * XS_CH;

                float G[6], Bv[6], E[6], ctrv[4], cm[6];
#pragma unroll
                for (int jp = 0; jp < 3; jp++) {
                    uint64_t av[3], dv[3];
#pragma unroll
                    for (int dy = 0; dy < 3; dy++) {
                        int idx = (ly + dy) * XROW + 4 * tx4 + 2 * jp;
                        uint64_t vm = *(const uint64_t*)(base + s0 * XS_PLANE + idx);
                        uint64_t vc = *(const uint64_t*)(base + s1 * XS_PLANE + idx);
                        uint64_t vp = *(const uint64_t*)(base + s2 * XS_PLANE + idx);
                        av[dy] = f2add(f2fma(TWO2, vc, vm), vp);
                        dv[dy] = f2fma(NEG2, vm, vp);
                        if (c == 3) {
                            float2 m_ = upk(vm), c_ = upk(vc), p_ = upk(vp);
                            float m0 = fmaxf(fmaxf(m_.x, c_.x), p_.x);
                            float m1 = fmaxf(fmaxf(m_.y, c_.y), p_.y);
                            if (dy == 0) { cm[2 * jp] = m0; cm[2 * jp + 1] = m1; }
                            else { cm[2 * jp] = fmaxf(cm[2 * jp], m0);
                                   cm[2 * jp + 1] = fmaxf(cm[2 * jp + 1], m1); }
                        }
                        if (dy == 1) {
                            float2 c_ = upk(vc);
                            if (jp == 0) ctrv[0] = c_.y;
                            if (jp == 1) { ctrv[1] = c_.x; ctrv[2] = c_.y; }
                            if (jp == 2) ctrv[3] = c_.x;
                        }
                    }
                    float2 g2 = upk(f2add(f2fma(TWO2, av[1], av[0]), av[2]));
                    float2 b2 = upk(f2fma(NEG2, av[0], av[2]));
                    float2 e2 = upk(f2add(f2fma(TWO2, dv[1], dv[0]), dv[2]));
                    G[2 * jp] = g2.x;  G[2 * jp + 1] = g2.y;
                    Bv[2 * jp] = b2.x; Bv[2 * jp + 1] = b2.y;
                    E[2 * jp] = e2.x;  E[2 * jp + 1] = e2.y;
                }
#pragma unroll
                for (int v = 0; v < 4; v++) {
                    st[ci][v][0] = ctrv[v];
                    st[ci][v][1] = G[v + 2] - G[v];
                    st[ci][v][2] = fmaf(2.f, Bv[v + 1], Bv[v]) + Bv[v + 2];
                    st[ci][v][3] = fmaf(2.f, E[v + 1], E[v]) + E[v + 2];
                }
                if (c == 3) {
                    uchar4 pre;
                    pre.x = (fmaxf(fmaxf(cm[0], cm[1]), cm[2]) > 0.1f) ? 1 : 0;
                    pre.y = (fmaxf(fmaxf(cm[1], cm[2]), cm[3]) > 0.1f) ? 1 : 0;
                    pre.z = (fmaxf(fmaxf(cm[2], cm[3]), cm[4]) > 0.1f) ? 1 : 0;
                    pre.w = (fmaxf(fmaxf(cm[3], cm[4]), cm[5]) > 0.1f) ? 1 : 0;
                    *(uchar4*)(g_pre + voxbase) = pre;
                }
            }
#pragma unroll
            for (int v = 0; v < 4; v++) {
                int row = lrow0 + v;
                uint4 o;
                o.x = pack_bf16x2(st[0][v][0], st[0][v][1]);
                o.y = pack_bf16x2(st[0][v][2], st[0][v][3]);
                o.z = pack_bf16x2(st[1][v][0], st[1][v][1]);
                o.w = pack_bf16x2(st[1][v][2], st[1][v][3]);
                *(uint4*)(YS + row * 128 + ((cpgrp ^ YSW(row)) << 4)) = o;
            }
        }
        __syncthreads();

        // -------- stoch prefetch --------
        float mvals[2];
#pragma unroll
        for (int vv = 0; vv < 2; vv++) {
            int lv = w * 16 + vv * 8 + g;
            size_t gvox = (((size_t)b * SS + z) * SS + ty0 + (lv >> 4)) * SS + tx0 + (lv & 15);
            mvals[vv] = stoch[gvox];
        }

        // -------- plane z+2 -> registers (LDG now, STS after nc=0) --------
        const int zp = z + 2;
        const bool doPf = (zp <= z0 + TZ);
        const bool zin  = doPf && (zp < SS);
        float4 pfv[NPF];
#pragma unroll
        for (int q = 0; q < NPF; q++) {
            pfv[q] = make_float4(0.f, 0.f, 0.f, 0.f);
            int cid = tid + 256 * q;
            if (zin && cid < 4 * XS_PLANE) {
                int cell = cid >> 2, part = cid & 3;
                int hy = cell / XROW - 1 + ty0;
                int wx = cell % XROW - 1 + tx0;
                if (hy >= 0 && hy < SS && wx >= 0 && wx < SS) {
                    const float4* p = (const float4*)(x +
                        ((((size_t)b * SS + zp) * SS + hy) * SS + wx) * SC);
                    pfv[q] = p[part];
                }
            }
        }

        // ---------------- GEMM phase ----------------
        uint32_t A[4][4];
#pragma unroll
        for (int kt = 0; kt < 4; kt++) {
            int r   = w * 16 + (lane & 15);
            int c16 = kt * 2 + (lane >> 4);
            uint32_t addr = smem_u32(YS) + r * 128 + ((c16 ^ YSW(r)) << 4);
            LDMATRIX_X4(A[kt], addr);
        }

        float dxacc[2][4];
#pragma unroll
        for (int i = 0; i < 8; i++) ((float*)dxacc)[i] = 0.f;

#pragma unroll
        for (int nc = 0; nc < 4; nc++) {
            float hc[4][4];
#pragma unroll
            for (int i = 0; i < 16; i++) ((float*)hc)[i] = 0.f;

#pragma unroll
            for (int kt = 0; kt < 4; kt++) {
#pragma unroll
                for (int pair = 0; pair < 2; pair++) {
                    int n_row = nc * 32 + pair * 16 + ((sel >> 1) << 3) + l7;
                    int c16 = kt * 2 + (sel & 1);
                    uint32_t addr = smem_u32(W0S) + n_row * 128 + ((c16 ^ YSW(n_row)) << 4);
                    uint32_t bf[4];
                    LDMATRIX_X4(bf, addr);
                    mma_bf16(hc[pair * 2],     A[kt], make_uint2(bf[0], bf[1]));
                    mma_bf16(hc[pair * 2 + 1], A[kt], make_uint2(bf[2], bf[3]));
                }
            }

            uint32_t a2[2][4];
#pragma unroll
            for (int n8 = 0; n8 < 4; n8++) {
                uint64_t bb2 = *(const uint64_t*)(b0 + nc * 32 + n8 * 8 + 2 * tg);
                int kt2 = n8 >> 1, half = n8 & 1;
                float2 p01 = upk(f2add(pk(hc[n8][0], hc[n8][1]), bb2));
                float2 p23 = upk(f2add(pk(hc[n8][2], hc[n8][3]), bb2));
                a2[kt2][half * 2 + 0] = pack_bf16x2(fmaxf(p01.x, 0.f), fmaxf(p01.y, 0.f));
                a2[kt2][half * 2 + 1] = pack_bf16x2(fmaxf(p23.x, 0.f), fmaxf(p23.y, 0.f));
            }

#pragma unroll
            for (int kk = 0; kk < 2; kk++) {
                int kt2g = nc * 2 + kk;
                int halfw = kt2g >> 2;
                int cb = (kt2g & 3) * 2 + (sel & 1);
                int r = halfw * 16 + ((sel >> 1) << 3) + l7;
                uint32_t addr = smem_u32(W1S) + r * 128 + ((cb ^ YSW(r)) << 4);
                uint32_t bf[4];
                LDMATRIX_X4(bf, addr);
                mma_bf16(dxacc[0], a2[kk], make_uint2(bf[0], bf[1]));
                mma_bf16(dxacc[1], a2[kk], make_uint2(bf[2], bf[3]));
            }

            // drain plane prefetch after nc=0 (DRAM latency elapsed)
            if (nc == 0 && doPf) {
                const int slot = (z + 2) % 3;
#pragma unroll
                for (int q = 0; q < NPF; q++) {
                    int cid = tid + 256 * q;
                    if (cid < 4 * XS_PLANE) {
                        int cell = cid >> 2, part = cid & 3;
                        float* d = XS + 4 * part * XS_CH + slot * XS_PLANE + cell;
                        d[0]         = pfv[q].x;
                        d[XS_CH]     = pfv[q].y;
                        d[2 * XS_CH] = pfv[q].z;
                        d[3 * XS_CH] = pfv[q].w;
                    }
                }
            }
        }

        // ------------- epilogue: out = x + dx*mask (x from XS smem) ----------
#pragma unroll
        for (int vv = 0; vv < 2; vv++) {
            int lv = w * 16 + vv * 8 + g;
            int y_l = lv >> 4, x_l = lv & 15;
            size_t gvox = (((size_t)b * SS + z) * SS + ty0 + y_l) * SS + tx0 + x_l;
            float m = (mvals[vv] > 0.5f) ? 1.f : 0.f;
            const int xsi = s1 * XS_PLANE + (y_l + 1) * XROW + (x_l + 1);
#pragma unroll
            for (int n8o = 0; n8o < 2; n8o++) {
                int c = n8o * 8 + 2 * tg;
                float2 xv;
                xv.x = XS[(c + 0) * XS_CH + xsi];
                xv.y = XS[(c + 1) * XS_CH + xsi];
                xv.x += dxacc[n8o][vv * 2 + 0] * m;
                xv.y += dxacc[n8o][vv * 2 + 1] * m;
                *(float2*)(out + gvox * 16 + c) = xv;
                if (n8o == 0 && tg == 1) G_ALPHA[gvox] = xv.y;
            }
        }
        __syncthreads();
    }
}

// ================= kill pass: zero voxels where life == 0 (4-wide) ===========
__global__ __launch_bounds__(256)
void nca_kill(float* __restrict__ out) {
    const int t = blockIdx.x * 256 + threadIdx.x;
    const int b  = t >> 16;
    const int r  = t & 65535;
    const int d  = r >> 10;
    const int h  = (r >> 4) & 63;
    const int w4 = (r & 15) << 2;
    const int v0 = ((b * SS + d) * SS + h) * SS + w4;

    const uint32_t pv = *(const uint32_t*)(g_pre + v0);

    float cm[6];
#pragma unroll
    for (int j = 0; j < 6; j++) cm[j] = -1e30f;

    if (pv != 0) {
#pragma unroll
        for (int dz = -1; dz <= 1; dz++) {
            int dd = d + dz;
            if (dd < 0 || dd >= SS) continue;
#pragma unroll
            for (int dy = -1; dy <= 1; dy++) {
                int hh = h + dy;
                if (hh < 0 || hh >= SS) continue;
                const float* row = G_ALPHA + ((b * SS + dd) * SS + hh) * SS + (w4 - 1);
#pragma unroll
                for (int j = 0; j < 6; j++)
                    cm[j] = fmaxf(cm[j], row[j]);
            }
        }
        if (w4 == 0)  cm[0] = -1e30f;
        if (w4 == 60) cm[5] = -1e30f;
    }

#pragma unroll
    for (int i = 0; i < 4; i++) {
        bool life = (((pv >> (8 * i)) & 255u) != 0u) &&
                    (fmaxf(fmaxf(cm[i], cm[i + 1]), cm[i + 2]) > 0.1f);
        if (!life) {
            float4 zz = make_float4(0.f, 0.f, 0.f, 0.f);
            float4* o = (float4*)out + (size_t)(v0 + i) * 4;
#pragma unroll
            for (int q = 0; q < 4; q++) o[q] = zz;
        }
    }
}

extern "C" void kernel_launch(void* const* d_in, const int* in_sizes, int n_in,
                              void* d_out, int out_size) {
    const float* x     = (const float*)d_in[0];
    const float* w0    = (const float*)d_in[1];
    const float* b0    = (const float*)d_in[2];
    const float* w1    = (const float*)d_in[3];
    const float* stoch = (const float*)d_in[4];

    cudaFuncSetAttribute(nca_fused, cudaFuncAttributeMaxDynamicSharedMemorySize, F_SMEM_BYTES);

    dim3 gridF(SS / TX, SS / TY, SB * (SS / TZ));   // (4, 8, 64) = 2048 CTAs
    nca_fused<<<gridF, 256, F_SMEM_BYTES>>>(x, w0, w1, b0, stoch, (float*)d_out);

    nca_kill<<<NVOX / 4 / 256, 256>>>((float*)d_out);
}

// round 15
// speedup vs baseline: 1.2198x; 1.2198x over previous
#include <cuda_runtime.h>
#include <cuda_bf16.h>
#include <cstdint>

// NCA 3D update step — fused conv+GEMM (bf16 HMMA), 16x16 tile, 2 CTAs/SM
// (R13 configuration), f32x2 packed conv math, ldmatrix B operands,
// register-staged plane prefetch. Kill pass with center-alpha fast path.

#define SB 4
#define SS 64
#define SC 16
#define NVOX (SB * SS * SS * SS)

__device__ float         g_alpha_buf[NVOX + 32];
#define G_ALPHA (g_alpha_buf + 16)
__device__ unsigned char g_pre[NVOX];

__device__ __forceinline__ uint32_t smem_u32(const void* p) {
    uint32_t a;
    asm("{ .reg .u64 t; cvta.to.shared.u64 t, %1; cvt.u32.u64 %0, t; }" : "=r"(a) : "l"(p));
    return a;
}
__device__ __forceinline__ uint32_t pack_bf16x2(float lo, float hi) {
    uint32_t r;
    asm("cvt.rn.bf16x2.f32 %0, %1, %2;" : "=r"(r) : "f"(hi), "f"(lo));
    return r;
}
__device__ __forceinline__ void mma_bf16(float* c, const uint32_t* a, const uint2 b) {
    asm volatile(
        "mma.sync.aligned.m16n8k16.row.col.f32.bf16.bf16.f32 "
        "{%0,%1,%2,%3}, {%4,%5,%6,%7}, {%8,%9}, {%0,%1,%2,%3};"
        : "+f"(c[0]), "+f"(c[1]), "+f"(c[2]), "+f"(c[3])
        : "r"(a[0]), "r"(a[1]), "r"(a[2]), "r"(a[3]), "r"(b.x), "r"(b.y));
}
#define LDMATRIX_X4(r, addr)                                                   \
    asm volatile("ldmatrix.sync.aligned.m8n8.x4.shared.b16 {%0,%1,%2,%3}, [%4];" \
        : "=r"((r)[0]), "=r"((r)[1]), "=r"((r)[2]), "=r"((r)[3]) : "r"(addr))

__device__ __forceinline__ uint64_t f2fma(uint64_t a, uint64_t b, uint64_t c) {
    uint64_t d; asm("fma.rn.f32x2 %0, %1, %2, %3;" : "=l"(d) : "l"(a), "l"(b), "l"(c)); return d;
}
__device__ __forceinline__ uint64_t f2add(uint64_t a, uint64_t b) {
    uint64_t d; asm("add.rn.f32x2 %0, %1, %2;" : "=l"(d) : "l"(a), "l"(b)); return d;
}
__device__ __forceinline__ float2 upk(uint64_t v) {
    uint32_t lo, hi; asm("mov.b64 {%0, %1}, %2;" : "=r"(lo), "=r"(hi) : "l"(v));
    return make_float2(__uint_as_float(lo), __uint_as_float(hi));
}
__device__ __forceinline__ uint64_t pk(float x, float y) {
    uint64_t v;
    asm("mov.b64 %0, {%1, %2};" : "=l"(v) : "r"(__float_as_uint(x)), "r"(__float_as_uint(y)));
    return v;
}
#define TWO2 0x4000000040000000ull
#define NEG2 0xBF800000BF800000ull

#define YSW(row) (((row) & 7) ^ (((row) >> 4) & 7))

#define TY 16
#define TX 16
#define TZ 8
#define XROW 18
#define XS_PLANE (18 * XROW)      // 324
#define XS_CH    (3 * XS_PLANE)   // 972
#define XS_BYTES (16 * XS_CH * 4) // 62208
#define YS_BYTES (256 * 128)      // 32768
#define F_SMEM_BYTES (XS_BYTES + YS_BYTES + 16384 + 4096)   // 115456 -> 2 CTAs/SM

__device__ __forceinline__ void load_plane(float* XS, const float* __restrict__ x,
                                           int b, int zp, int ty0, int tx0,
                                           int slot, int tid) {
    const bool zin = (zp >= 0 && zp < SS);
    for (int i = tid; i < 18 * 18; i += 256) {
        int hy = i / 18;
        int wx = i % 18;
        int dst = slot * XS_PLANE + hy * XROW + wx;
        int gy2 = hy - 1 + ty0, gx2 = wx - 1 + tx0;
        if (zin && gy2 >= 0 && gy2 < SS && gx2 >= 0 && gx2 < SS) {
            const float4* p = (const float4*)(x + ((((size_t)b * SS + zp) * SS + gy2) * SS + gx2) * SC);
#pragma unroll
            for (int q = 0; q < 4; q++) {
                float4 v = p[q];
                XS[(4 * q + 0) * XS_CH + dst] = v.x;
                XS[(4 * q + 1) * XS_CH + dst] = v.y;
                XS[(4 * q + 2) * XS_CH + dst] = v.z;
                XS[(4 * q + 3) * XS_CH + dst] = v.w;
            }
        } else {
#pragma unroll
            for (int c = 0; c < 16; c++) XS[c * XS_CH + dst] = 0.f;
        }
    }
}

#define NPF 6   // 1296 16B-chunks / 256 threads

__global__ __launch_bounds__(256, 2)
void nca_fused(const float* __restrict__ x, const float* __restrict__ w0g,
               const float* __restrict__ w1g, const float* __restrict__ b0,
               const float* __restrict__ stoch, float* __restrict__ out) {
    extern __shared__ float SM[];
    float*   XS  = SM;
    uint8_t* YS  = (uint8_t*)(SM + 16 * XS_CH);
    uint8_t* W0S = YS + YS_BYTES;
    uint8_t* W1S = W0S + 16384;

    const int tid = threadIdx.x;

    for (int t = tid; t < 128 * 32; t += 256) {
        int n = t >> 5, k2 = t & 31;
        float e[2];
#pragma unroll
        for (int q = 0; q < 2; q++) {
            int kp = 2 * k2 + q;
            int ko = (kp & 3) * 16 + (kp >> 2);
            float s = (ko >= 16) ? (1.f / 32.f) : 1.f;
            e[q] = w0g[n * 64 + ko] * s;
        }
        int c16 = k2 >> 2;
        *(uint32_t*)(W0S + n * 128 + ((c16 ^ YSW(n)) << 4) + (k2 & 3) * 4) =
            pack_bf16x2(e[0], e[1]);
    }
    for (int t = tid; t < 32 * 32; t += 256) {
        int r = t >> 5, k2 = t & 31;
        int n = r & 15, half = r >> 4;
        int k = half * 64 + 2 * k2;
        int c16 = k2 >> 2;
        *(uint32_t*)(W1S + r * 128 + ((c16 ^ YSW(r)) << 4) + (k2 & 3) * 4) =
            pack_bf16x2(w1g[n * 128 + k], w1g[n * 128 + k + 1]);
    }

    const int b   = blockIdx.z >> 3;
    const int z0  = (blockIdx.z & 7) * TZ;
    const int ty0 = blockIdx.y * TY;
    const int tx0 = blockIdx.x * TX;

    load_plane(XS, x, b, z0 - 1, ty0, tx0, ((z0 - 1) + 3) % 3, tid);
    load_plane(XS, x, b, z0,     ty0, tx0, z0 % 3,             tid);
    load_plane(XS, x, b, z0 + 1, ty0, tx0, (z0 + 1) % 3,       tid);

    const int cg  = tid >> 6;
    const int sub = tid & 63;
    const int ly  = sub & 15;
    const int tx4 = sub >> 4;
    const int gh  = ty0 + ly;
    const int gx0 = tx0 + 4 * tx4;

    const int w    = tid >> 5;
    const int lane = tid & 31;
    const int g    = lane >> 2;
    const int tg   = lane & 3;
    const int l7   = lane & 7;
    const int sel  = lane >> 3;

    int pf_dst[NPF];
    int pf_gy[NPF], pf_gx[NPF], pf_part[NPF];
    bool pf_in[NPF];
#pragma unroll
    for (int q = 0; q < NPF; q++) {
        int cid = tid + 256 * q;
        bool ok = cid < 1296;
        int cell = ok ? (cid >> 2) : 0;
        int part = cid & 3;
        int hy = cell / 18, wx = cell % 18;
        pf_dst[q]  = hy * XROW + wx;
        pf_part[q] = part;
        pf_gy[q]   = hy - 1 + ty0;
        pf_gx[q]   = wx - 1 + tx0;
        pf_in[q]   = ok && pf_gy[q] >= 0 && pf_gy[q] < SS && pf_gx[q] >= 0 && pf_gx[q] < SS;
        if (!ok) { pf_dst[q] = -1; }
    }

    __syncthreads();

    for (int z = z0; z < z0 + TZ; z++) {
        const int s0 = ((z - 1) + 3) % 3, s1 = z % 3, s2 = (z + 1) % 3;
        const size_t voxbase = (((size_t)b * SS + z) * SS + gh) * SS + gx0;
        const int lrow0 = ly * TX + 4 * tx4;

#pragma unroll
        for (int cpair = 0; cpair < 2; cpair++) {
            float st[2][4][4];
#pragma unroll
            for (int ci = 0; ci < 2; ci++) {
                const int c = cg * 4 + cpair * 2 + ci;
                const float* base = XS + c * XS_CH;

                uint64_t a2r[3][3], d2r[3][3];
                float ctrv[4], cm[6];
#pragma unroll
                for (int dy = 0; dy < 3; dy++) {
#pragma unroll
                    for (int jp = 0; jp < 3; jp++) {
                        int idx = (ly + dy) * XROW + 4 * tx4 + 2 * jp;
                        uint64_t vm = *(const uint64_t*)(base + s0 * XS_PLANE + idx);
                        uint64_t vc = *(const uint64_t*)(base + s1 * XS_PLANE + idx);
                        uint64_t vp = *(const uint64_t*)(base + s2 * XS_PLANE + idx);
                        a2r[dy][jp] = f2add(f2fma(TWO2, vc, vm), vp);
                        d2r[dy][jp] = f2fma(NEG2, vm, vp);
                        if (c == 3) {
                            float2 m_ = upk(vm), c_ = upk(vc), p_ = upk(vp);
                            float m0 = fmaxf(fmaxf(m_.x, c_.x), p_.x);
                            float m1 = fmaxf(fmaxf(m_.y, c_.y), p_.y);
                            if (dy == 0) { cm[2 * jp] = m0; cm[2 * jp + 1] = m1; }
                            else { cm[2 * jp] = fmaxf(cm[2 * jp], m0);
                                   cm[2 * jp + 1] = fmaxf(cm[2 * jp + 1], m1); }
                        }
                        if (dy == 1) {
                            float2 c_ = upk(vc);
                            if (jp == 0) ctrv[0] = c_.y;
                            if (jp == 1) { ctrv[1] = c_.x; ctrv[2] = c_.y; }
                            if (jp == 2) ctrv[3] = c_.x;
                        }
                    }
                }
                float G[6], Bv[6], E[6];
#pragma unroll
                for (int jp = 0; jp < 3; jp++) {
                    float2 g2 = upk(f2add(f2fma(TWO2, a2r[1][jp], a2r[0][jp]), a2r[2][jp]));
                    float2 b2 = upk(f2fma(NEG2, a2r[0][jp], a2r[2][jp]));
                    float2 e2 = upk(f2add(f2fma(TWO2, d2r[1][jp], d2r[0][jp]), d2r[2][jp]));
                    G[2 * jp] = g2.x;  G[2 * jp + 1] = g2.y;
                    Bv[2 * jp] = b2.x; Bv[2 * jp + 1] = b2.y;
                    E[2 * jp] = e2.x;  E[2 * jp + 1] = e2.y;
                }
#pragma unroll
                for (int v = 0; v < 4; v++) {
                    st[ci][v][0] = ctrv[v];
                    st[ci][v][1] = G[v + 2] - G[v];
                    st[ci][v][2] = fmaf(2.f, Bv[v + 1], Bv[v]) + Bv[v + 2];
                    st[ci][v][3] = fmaf(2.f, E[v + 1], E[v]) + E[v + 2];
                }
                if (c == 3) {
                    uchar4 pre;
                    pre.x = (fmaxf(fmaxf(cm[0], cm[1]), cm[2]) > 0.1f) ? 1 : 0;
                    pre.y = (fmaxf(fmaxf(cm[1], cm[2]), cm[3]) > 0.1f) ? 1 : 0;
                    pre.z = (fmaxf(fmaxf(cm[2], cm[3]), cm[4]) > 0.1f) ? 1 : 0;
                    pre.w = (fmaxf(fmaxf(cm[3], cm[4]), cm[5]) > 0.1f) ? 1 : 0;
                    *(uchar4*)(g_pre + voxbase) = pre;
                }
            }
            const int c16 = cg * 2 + cpair;
#pragma unroll
            for (int v = 0; v < 4; v++) {
                int row = lrow0 + v;
                uint4 o;
                o.x = pack_bf16x2(st[0][v][0], st[0][v][1]);
                o.y = pack_bf16x2(st[0][v][2], st[0][v][3]);
                o.z = pack_bf16x2(st[1][v][0], st[1][v][1]);
                o.w = pack_bf16x2(st[1][v][2], st[1][v][3]);
                *(uint4*)(YS + row * 128 + ((c16 ^ YSW(row)) << 4)) = o;
            }
        }
        __syncthreads();

        float mvals[4];
#pragma unroll
        for (int mt = 0; mt < 2; mt++)
#pragma unroll
            for (int vv = 0; vv < 2; vv++) {
                int lv = w * 32 + mt * 16 + g + vv * 8;
                size_t gvox = (((size_t)b * SS + z) * SS + ty0 + (lv >> 4)) * SS + tx0 + (lv & 15);
                mvals[mt * 2 + vv] = stoch[gvox];
            }

        const int zp = z + 2;
        const bool doPf = (zp <= z0 + TZ);
        const bool zin  = doPf && (zp < SS);
        float4 pfv[NPF];
#pragma unroll
        for (int q = 0; q < NPF; q++) {
            pfv[q] = make_float4(0.f, 0.f, 0.f, 0.f);
            if (zin && pf_in[q]) {
                const float4* p = (const float4*)(x +
                    ((((size_t)b * SS + zp) * SS + pf_gy[q]) * SS + pf_gx[q]) * SC);
                pfv[q] = p[pf_part[q]];
            }
        }

        uint32_t A[2][4][4];
#pragma unroll
        for (int mt = 0; mt < 2; mt++) {
#pragma unroll
            for (int kt = 0; kt < 4; kt++) {
                int r   = w * 32 + mt * 16 + (lane & 15);
                int c16 = kt * 2 + (lane >> 4);
                uint32_t addr = smem_u32(YS) + r * 128 + ((c16 ^ YSW(r)) << 4);
                LDMATRIX_X4(A[mt][kt], addr);
            }
        }

        float dxacc[2][2][4];
#pragma unroll
        for (int i = 0; i < 16; i++) ((float*)dxacc)[i] = 0.f;

#pragma unroll
        for (int nc = 0; nc < 4; nc++) {
            float hc[2][4][4];
#pragma unroll
            for (int i = 0; i < 32; i++) ((float*)hc)[i] = 0.f;

#pragma unroll
            for (int kt = 0; kt < 4; kt++) {
#pragma unroll
                for (int pair = 0; pair < 2; pair++) {
                    int n_row = nc * 32 + pair * 16 + ((sel >> 1) << 3) + l7;
                    int c16 = kt * 2 + (sel & 1);
                    uint32_t addr = smem_u32(W0S) + n_row * 128 + ((c16 ^ YSW(n_row)) << 4);
                    uint32_t bf[4];
                    LDMATRIX_X4(bf, addr);
                    uint2 bA = make_uint2(bf[0], bf[1]);
                    uint2 bB = make_uint2(bf[2], bf[3]);
                    mma_bf16(hc[0][pair * 2],     A[0][kt], bA);
                    mma_bf16(hc[1][pair * 2],     A[1][kt], bA);
                    mma_bf16(hc[0][pair * 2 + 1], A[0][kt], bB);
                    mma_bf16(hc[1][pair * 2 + 1], A[1][kt], bB);
                }
            }

            uint32_t a2[2][2][4];
#pragma unroll
            for (int n8 = 0; n8 < 4; n8++) {
                uint64_t bb2 = *(const uint64_t*)(b0 + nc * 32 + n8 * 8 + 2 * tg);
                int kt2 = n8 >> 1, half = n8 & 1;
#pragma unroll
                for (int mt = 0; mt < 2; mt++) {
                    float2 p01 = upk(f2add(pk(hc[mt][n8][0], hc[mt][n8][1]), bb2));
                    float2 p23 = upk(f2add(pk(hc[mt][n8][2], hc[mt][n8][3]), bb2));
                    a2[mt][kt2][half * 2 + 0] =
                        pack_bf16x2(fmaxf(p01.x, 0.f), fmaxf(p01.y, 0.f));
                    a2[mt][kt2][half * 2 + 1] =
                        pack_bf16x2(fmaxf(p23.x, 0.f), fmaxf(p23.y, 0.f));
                }
            }

#pragma unroll
            for (int kk = 0; kk < 2; kk++) {
                int kt2g = nc * 2 + kk;
                int halfw = kt2g >> 2;
                int cb = (kt2g & 3) * 2 + (sel & 1);
                int r = halfw * 16 + ((sel >> 1) << 3) + l7;
                uint32_t addr = smem_u32(W1S) + r * 128 + ((cb ^ YSW(r)) << 4);
                uint32_t bf[4];
                LDMATRIX_X4(bf, addr);
                uint2 b2A = make_uint2(bf[0], bf[1]);
                uint2 b2B = make_uint2(bf[2], bf[3]);
                mma_bf16(dxacc[0][0], a2[0][kk], b2A);
                mma_bf16(dxacc[1][0], a2[1][kk], b2A);
                mma_bf16(dxacc[0][1], a2[0][kk], b2B);
                mma_bf16(dxacc[1][1], a2[1][kk], b2B);
            }

            if (nc == 0 && doPf) {
                const int slot = (z + 2) % 3;
#pragma unroll
                for (int q = 0; q < NPF; q++) {
                    if (pf_dst[q] >= 0) {
                        float* d = XS + 4 * pf_part[q] * XS_CH + slot * XS_PLANE + pf_dst[q];
                        d[0]          = pfv[q].x;
                        d[XS_CH]      = pfv[q].y;
                        d[2 * XS_CH]  = pfv[q].z;
                        d[3 * XS_CH]  = pfv[q].w;
                    }
                }
            }
        }

#pragma unroll
        for (int mt = 0; mt < 2; mt++) {
#pragma unroll
            for (int vv = 0; vv < 2; vv++) {
                int lv = w * 32 + mt * 16 + g + vv * 8;
                int y_l = lv >> 4, x_l = lv & 15;
                size_t gvox = (((size_t)b * SS + z) * SS + ty0 + y_l) * SS + tx0 + x_l;
                float m = (mvals[mt * 2 + vv] > 0.5f) ? 1.f : 0.f;
                const int xsi = s1 * XS_PLANE + (y_l + 1) * XROW + (x_l + 1);
#pragma unroll
                for (int n8o = 0; n8o < 2; n8o++) {
                    int c = n8o * 8 + 2 * tg;
                    float2 xv;
                    xv.x = XS[(c + 0) * XS_CH + xsi];
                    xv.y = XS[(c + 1) * XS_CH + xsi];
                    xv.x += dxacc[mt][n8o][vv * 2 + 0] * m;
                    xv.y += dxacc[mt][n8o][vv * 2 + 1] * m;
                    *(float2*)(out + gvox * 16 + c) = xv;
                    if (n8o == 0 && tg == 1) G_ALPHA[gvox] = xv.y;
                }
            }
        }
        __syncthreads();
    }
}

// ============ kill pass: center-alpha fast path + exact fallback =============
__global__ __launch_bounds__(256)
void nca_kill(float* __restrict__ out) {
    const int t = blockIdx.x * 256 + threadIdx.x;
    const int b  = t >> 16;
    const int r  = t & 65535;
    const int d  = r >> 10;
    const int h  = (r >> 4) & 63;
    const int w4 = (r & 15) << 2;
    const int v0 = ((b * SS + d) * SS + h) * SS + w4;

    // fast path: if all 4 pre-bits set AND all 4 center alphas > 0.1, every
    // voxel's 3x3x3 window (which contains its center) passes -> life=1 for
    // all 4 -> nothing to write. Exact for any input.
    const uint32_t pv = *(const uint32_t*)(g_pre + v0);
    const float4 ca = *(const float4*)(G_ALPHA + v0);    // 16B-aligned
    if (pv == 0x01010101u &&
        ca.x > 0.1f && ca.y > 0.1f && ca.z > 0.1f && ca.w > 0.1f)
        return;

    float cm[6];
#pragma unroll
    for (int j = 0; j < 6; j++) cm[j] = -1e30f;

    if (pv != 0) {
#pragma unroll
        for (int dz = -1; dz <= 1; dz++) {
            int dd = d + dz;
            if (dd < 0 || dd >= SS) continue;
#pragma unroll
            for (int dy = -1; dy <= 1; dy++) {
                int hh = h + dy;
                if (hh < 0 || hh >= SS) continue;
                const float* row = G_ALPHA + ((b * SS + dd) * SS + hh) * SS + (w4 - 1);
#pragma unroll
                for (int j = 0; j < 6; j++)
                    cm[j] = fmaxf(cm[j], row[j]);
            }
        }
        if (w4 == 0)  cm[0] = -1e30f;
        if (w4 == 60) cm[5] = -1e30f;
    }

#pragma unroll
    for (int i = 0; i < 4; i++) {
        bool life = (((pv >> (8 * i)) & 255u) != 0u) &&
                    (fmaxf(fmaxf(cm[i], cm[i + 1]), cm[i + 2]) > 0.1f);
        if (!life) {
            float4 zz = make_float4(0.f, 0.f, 0.f, 0.f);
            float4* o = (float4*)out + (size_t)(v0 + i) * 4;
#pragma unroll
            for (int q = 0; q < 4; q++) o[q] = zz;
        }
    }
}

extern "C" void kernel_launch(void* const* d_in, const int* in_sizes, int n_in,
                              void* d_out, int out_size) {
    const float* x     = (const float*)d_in[0];
    const float* w0    = (const float*)d_in[1];
    const float* b0    = (const float*)d_in[2];
    const float* w1    = (const float*)d_in[3];
    const float* stoch = (const float*)d_in[4];

    cudaFuncSetAttribute(nca_fused, cudaFuncAttributeMaxDynamicSharedMemorySize, F_SMEM_BYTES);

    dim3 gridF(SS / TX, SS / TY, SB * (SS / TZ));   // (4, 4, 32) = 512 CTAs
    nca_fused<<<gridF, 256, F_SMEM_BYTES>>>(x, w0, w1, b0, stoch, (float*)d_out);

    nca_kill<<<NVOX / 4 / 256, 256>>>((float*)d_out);
}